// round 13
// baseline (speedup 1.0000x reference)
#include <cuda_runtime.h>
#include <cuda_fp16.h>
#include <cstdint>

#define EMB   1024
#define CTXT  2048
#define MROWS 4096   // BATCH * CTXT

// ---------------------------------------------------------------------------
// Device scratch (allocation-free rule)
// ---------------------------------------------------------------------------
__device__ __half g_xh[MROWS * EMB];         // x, fp16
__device__ __half g_wt[4][EMB * EMB];        // W^T [n][k] fp16 (q,k,v,o)
__device__ __half g_Qh[MROWS * EMB];         // (xWq+bq) * log2e/32, fp16
__device__ __half g_Kh[MROWS * EMB];         // fp16
__device__ __half g_Vh[MROWS * EMB];         // fp16 (row-major)
__device__ __half g_ao[MROWS * EMB];         // attention out fp16

// ---------------------------------------------------------------------------
__device__ __forceinline__ uint32_t smem_u32(const void* p) {
    uint32_t a;
    asm("{ .reg .u64 t; cvta.to.shared.u64 t, %1; cvt.u32.u64 %0, t; }"
        : "=r"(a) : "l"(p));
    return a;
}
__device__ __forceinline__ void cpa16(uint32_t s, const void* g) {
    asm volatile("cp.async.cg.shared.global [%0], [%1], 16;" :: "r"(s), "l"(g));
}
__device__ __forceinline__ uint32_t packh(float x, float y) {
    __half2 h = __floats2half2_rn(x, y);
    return *(uint32_t*)&h;
}
// pack two fp32 (<=0) and take 2^x in fp16x2
__device__ __forceinline__ uint32_t ex2pack(float x, float y) {
    uint32_t d = packh(x, y), r;
    asm("ex2.approx.f16x2 %0, %1;" : "=r"(r) : "r"(d));
    return r;
}
__device__ __forceinline__ uint32_t hmul2u(uint32_t a, uint32_t b) {
    uint32_t r;
    asm("mul.f16x2 %0, %1, %2;" : "=r"(r) : "r"(a), "r"(b));
    return r;
}

#define LDM4(r, a)                                                            \
    asm volatile("ldmatrix.sync.aligned.m8n8.x4.shared.b16 {%0,%1,%2,%3}, [%4];" \
        : "=r"((r)[0]), "=r"((r)[1]), "=r"((r)[2]), "=r"((r)[3]) : "r"(a))

#define LDM4T(r, a)                                                           \
    asm volatile("ldmatrix.sync.aligned.m8n8.x4.trans.shared.b16 {%0,%1,%2,%3}, [%4];" \
        : "=r"((r)[0]), "=r"((r)[1]), "=r"((r)[2]), "=r"((r)[3]) : "r"(a))

#define MMAH(c, a, b0, b1)                                                    \
    asm volatile("mma.sync.aligned.m16n8k16.row.col.f32.f16.f16.f32 "         \
        "{%0,%1,%2,%3}, {%4,%5,%6,%7}, {%8,%9}, {%0,%1,%2,%3};"               \
        : "+f"((c)[0]), "+f"((c)[1]), "+f"((c)[2]), "+f"((c)[3])              \
        : "r"((a)[0]), "r"((a)[1]), "r"((a)[2]), "r"((a)[3]), "r"(b0), "r"(b1))

// ---------------------------------------------------------------------------
// Prep kernels
// ---------------------------------------------------------------------------
__global__ __launch_bounds__(256) void conv_x_kernel(const float* __restrict__ x) {
    size_t i = ((size_t)blockIdx.x * 256 + threadIdx.x) * 8;
    float4 v0 = *(const float4*)(x + i);
    float4 v1 = *(const float4*)(x + i + 4);
    uint32_t h[4];
    h[0] = packh(v0.x, v0.y); h[1] = packh(v0.z, v0.w);
    h[2] = packh(v1.x, v1.y); h[3] = packh(v1.z, v1.w);
    *(uint4*)(g_xh + i) = *(uint4*)h;
}

// Transpose + convert weights: W[k][n] -> WT[n][k] fp16
__global__ __launch_bounds__(256) void conv_wt_kernel(
    const float* __restrict__ Wq, const float* __restrict__ Wk,
    const float* __restrict__ Wv, const float* __restrict__ Wo)
{
    __shared__ float ts[32][33];
    const int z = blockIdx.z;
    const float* W = (z == 0) ? Wq : (z == 1) ? Wk : (z == 2) ? Wv : Wo;
    const int row0 = blockIdx.y << 5;   // k
    const int col0 = blockIdx.x << 5;   // n
    const int c = threadIdx.x & 31, r8 = threadIdx.x >> 5;
#pragma unroll
    for (int it = 0; it < 4; ++it) {
        int r = it * 8 + r8;
        ts[r][c] = W[(size_t)(row0 + r) * EMB + col0 + c];
    }
    __syncthreads();
#pragma unroll
    for (int it = 0; it < 4; ++it) {
        int r = it * 8 + r8;
        g_wt[z][(size_t)(col0 + r) * EMB + row0 + c] = __float2half(ts[c][r]);
    }
}

// ---------------------------------------------------------------------------
// FP16 GEMM: C[64,128] tile, K=1024. 8 warps (4M x 2N), warp tile 16x64.
// BK=64 halves (128B rows), 3-stage cp.async -> 73KB smem -> 3 CTAs/SM.
// ---------------------------------------------------------------------------
#define GSTAGE 24576                 // A 8KB + B 16KB
#define GEMM_SMEM (1024 + 3 * GSTAGE)

__device__ void h_gemm_body(const __half* __restrict__ A,
                            const __half* __restrict__ B,
                            const float* __restrict__ bias,
                            float* __restrict__ Cf,      // fp32 out
                            __half* __restrict__ Ch,     // fp16 out
                            float scale,
                            int row0, int col0)
{
    extern __shared__ char smraw[];
    const uint32_t sb = (smem_u32(smraw) + 1023u) & ~1023u;

    const int tid  = threadIdx.x;
    const int lane = tid & 31;
    const int wid  = tid >> 5;
    const int g    = lane >> 2;
    const int t4   = lane & 3;
    const int wm   = wid & 3;     // 4 x 16 rows
    const int wn   = wid >> 2;    // 2 x 64 cols

    float acc[8][4];
#pragma unroll
    for (int j = 0; j < 8; ++j)
#pragma unroll
        for (int q = 0; q < 4; ++q) acc[j][q] = 0.f;

    uint32_t paA, paB[4];
    {
        const int rrA = (lane & 7) + ((lane >> 3) & 1) * 8;
        const int cpA = (lane >> 4) & 1;
        const int r = wm * 16 + rrA;
        paA = r * 128 + ((cpA ^ (r & 1)) << 4) + (((r >> 1) & 3) << 5);

        const int rrB = (lane & 7) + ((lane >> 4) & 1) * 8;
        const int cpB = (lane >> 3) & 1;
#pragma unroll
        for (int np = 0; np < 4; ++np) {
            int n = wn * 64 + np * 16 + rrB;
            paB[np] = 8192 + n * 128 + ((cpB ^ (n & 1)) << 4) + (((n >> 1) & 3) << 5);
        }
    }

    auto issue = [&](int kc, int st) {
        const uint32_t sbase = sb + st * GSTAGE;
        // A: 64 rows x 8 chunks = 512 units (2 iters)
#pragma unroll
        for (int it = 0; it < 2; ++it) {
            const int id = it * 256 + tid;
            const int r = id >> 3, c = id & 7;
            cpa16(sbase + r * 128 + ((c ^ (r & 7)) << 4),
                  A + (size_t)(row0 + r) * EMB + kc + c * 8);
        }
        // B: 128 rows x 8 chunks = 1024 units (4 iters)
#pragma unroll
        for (int it = 0; it < 4; ++it) {
            const int id = it * 256 + tid;
            const int r = id >> 3, c = id & 7;
            cpa16(sbase + 8192 + r * 128 + ((c ^ (r & 7)) << 4),
                  B + (size_t)(col0 + r) * EMB + kc + c * 8);
        }
        asm volatile("cp.async.commit_group;");
    };

    issue(0, 0);
    issue(64, 1);

    for (int c = 0; c < EMB / 64; ++c) {
        if (c + 1 < EMB / 64) {
            asm volatile("cp.async.wait_group 1;");
        } else {
            asm volatile("cp.async.wait_group 0;");
        }
        __syncthreads();
        if (c + 2 < EMB / 64) issue((c + 2) * 64, (c + 2) % 3);

        const uint32_t stb = sb + (c % 3) * GSTAGE;
#pragma unroll
        for (int s = 0; s < 4; ++s) {
            const uint32_t xs = (uint32_t)s << 5;
            uint32_t a[4], bg[4][4];
            LDM4(a, (stb + paA) ^ xs);
#pragma unroll
            for (int np = 0; np < 4; ++np) LDM4(bg[np], (stb + paB[np]) ^ xs);
#pragma unroll
            for (int nt = 0; nt < 8; ++nt)
                MMAH(acc[nt], a, bg[nt >> 1][(nt & 1) * 2],
                     bg[nt >> 1][(nt & 1) * 2 + 1]);
        }
    }

#pragma unroll
    for (int nt = 0; nt < 8; ++nt) {
        const int n = col0 + wn * 64 + nt * 8 + t4 * 2;
        const float bz0 = bias[n], bz1 = bias[n + 1];
        const int mr = row0 + wm * 16 + g;
        float p0 = acc[nt][0] + bz0, p1 = acc[nt][1] + bz1;
        float p2 = acc[nt][2] + bz0, p3 = acc[nt][3] + bz1;
        if (Ch) {
            *(uint32_t*)(Ch + (size_t)mr * EMB + n) = packh(p0 * scale, p1 * scale);
            *(uint32_t*)(Ch + (size_t)(mr + 8) * EMB + n) = packh(p2 * scale, p3 * scale);
        } else {
            *(float2*)(Cf + (size_t)mr * EMB + n) = float2{p0, p1};
            *(float2*)(Cf + (size_t)(mr + 8) * EMB + n) = float2{p2, p3};
        }
    }
}

__global__ __launch_bounds__(256, 3) void gemm_qkv_kernel(
    const float* __restrict__ bq, const float* __restrict__ bk,
    const float* __restrict__ bv)
{
    const int z = blockIdx.z;
    const int r0 = blockIdx.y << 6, c0 = blockIdx.x << 7;
    if (z == 0)   // fold 1/sqrt(1024) * log2(e) into Q
        h_gemm_body(g_xh, g_wt[0], bq, nullptr, g_Qh, 0.0450842190f, r0, c0);
    else if (z == 1)
        h_gemm_body(g_xh, g_wt[1], bk, nullptr, g_Kh, 1.0f, r0, c0);
    else
        h_gemm_body(g_xh, g_wt[2], bv, nullptr, g_Vh, 1.0f, r0, c0);
}

__global__ __launch_bounds__(256, 3) void gemm_out_kernel(
    const float* __restrict__ bo, float* __restrict__ out)
{
    h_gemm_body(g_ao, g_wt[3], bo, out, nullptr, 1.0f,
                blockIdx.y << 6, blockIdx.x << 7);
}

// ---------------------------------------------------------------------------
// FP16 flash attention, log2-domain softmax, fp16x2 ex2, ones-MMA row sums.
// BM=128 (8 warps x m16), fused BN=128 softmax (one rescale per 2 j-blocks).
// Grid: (T/128, B*H). smem: Q 16KB + 4 KV stages (K+V) 16KB each.
// ---------------------------------------------------------------------------
#define FSTG0 16384
#define FSTGSZ 16384
#define FLASH_SMEM (1024 + FSTG0 + 4 * FSTGSZ)   // 83 KB -> 2 CTAs/SM
#define HONES 0x3C003C00u   // half2(1.0, 1.0)

__global__ __launch_bounds__(256, 2) void flash_h_kernel()
{
    extern __shared__ char fsmraw[];
    const uint32_t sb = (smem_u32(fsmraw) + 1023u) & ~1023u;

    const int tid = threadIdx.x;
    const int lane = tid & 31, wid = tid >> 5;
    const int g = lane >> 2, t4 = lane & 3;
    const int bh = blockIdx.y, b = bh >> 4;
    const int qb = (int)(gridDim.x - 1 - blockIdx.x);   // longest first
    const int q0 = qb << 7;
    const size_t base = (size_t)b * CTXT;
    const int ch = (bh & 15) << 6;
    const int rbase = q0 + wid * 16;

    uint32_t paQ, paK[4], paVt[4];
    {
        const int rrA = (lane & 7) + ((lane >> 3) & 1) * 8;
        const int cpA = (lane >> 4) & 1;
        const int r = wid * 16 + rrA;
        paQ = r * 128 + ((cpA ^ (r & 1)) << 4) + (((r >> 1) & 3) << 5);

        const int rrB = (lane & 7) + ((lane >> 4) & 1) * 8;
        const int cpB = (lane >> 3) & 1;
#pragma unroll
        for (int np = 0; np < 4; ++np) {
            int n = np * 16 + rrB;
            paK[np] = n * 128 + ((cpB ^ (n & 1)) << 4) + (((n >> 1) & 3) << 5);
        }
        const int rrV = (lane & 7) + ((lane >> 3) & 1) * 8;   // j within 16
        const int cpV = (lane >> 4) & 1;                      // d chunk within 16
#pragma unroll
        for (int np = 0; np < 4; ++np) {
            int c = 2 * np + cpV;
            paVt[np] = 8192 + rrV * 128 + ((c ^ (rrV & 7)) << 4);
        }
    }

    // Q tile (group 0)
    for (int i = tid; i < 1024; i += 256) {
        const int r = i >> 3, c = i & 7;
        cpa16(sb + r * 128 + ((c ^ (r & 7)) << 4),
              g_Qh + (base + q0 + r) * EMB + ch + c * 8);
    }
    asm volatile("cp.async.commit_group;");

    auto issue_kv = [&](int j0, int st) {
        const uint32_t kb = sb + FSTG0 + st * FSTGSZ;
        for (int i = tid; i < 512; i += 256) {
            const int r = i >> 3, c = i & 7;
            const uint32_t so = r * 128 + ((c ^ (r & 7)) << 4);
            cpa16(kb + so, g_Kh + (base + j0 + r) * EMB + ch + c * 8);
            cpa16(kb + 8192 + so, g_Vh + (base + j0 + r) * EMB + ch + c * 8);
        }
        asm volatile("cp.async.commit_group;");
    };

    const int nblocks = qb * 2 + 2;   // always even
    issue_kv(0, 0);
    issue_kv(64, 1);

    uint32_t qf[4][4];                 // Q fragments, loaded once
    float o[8][4];
    float ol[4] = {0.f, 0.f, 0.f, 0.f};
#pragma unroll
    for (int nt = 0; nt < 8; ++nt)
#pragma unroll
        for (int q = 0; q < 4; ++q) o[nt][q] = 0.f;
    float m0 = -1e30f, m1 = -1e30f;

    for (int jb = 0; jb < nblocks; jb += 2) {
        asm volatile("cp.async.wait_group 0;");
        __syncthreads();
        if (jb == 0) {
#pragma unroll
            for (int s = 0; s < 4; ++s) LDM4(qf[s], (sb + paQ) ^ ((uint32_t)s << 5));
        }
        // prefetch next pair into stages consumed LAST pair (sync above protects)
        if (jb + 2 < nblocks) issue_kv((jb + 2) << 6, (jb + 2) & 3);
        if (jb + 3 < nblocks) issue_kv((jb + 3) << 6, (jb + 3) & 3);

        const int j0 = jb << 6;
        if (j0 > rbase + 15) continue;        // pair fully masked for this warp
        const bool do1 = (j0 + 64) <= rbase + 15;
        const uint32_t kb0 = sb + FSTG0 + (jb & 3) * FSTGSZ;
        const uint32_t kb1 = sb + FSTG0 + ((jb + 1) & 3) * FSTGSZ;

        float sc[8][4];

        // ================= S0 = Q K0^T =================
#pragma unroll
        for (int nt = 0; nt < 8; ++nt)
#pragma unroll
            for (int q = 0; q < 4; ++q) sc[nt][q] = 0.f;
#pragma unroll
        for (int s = 0; s < 4; ++s) {
            const uint32_t xs = (uint32_t)s << 5;
            uint32_t bg[4][4];
#pragma unroll
            for (int np = 0; np < 4; ++np) LDM4(bg[np], (kb0 + paK[np]) ^ xs);
#pragma unroll
            for (int nt = 0; nt < 8; ++nt)
                MMAH(sc[nt], qf[s], bg[nt >> 1][(nt & 1) * 2],
                     bg[nt >> 1][(nt & 1) * 2 + 1]);
        }
        if (j0 + 63 > rbase) {
            const int r0r = rbase + g, r1r = rbase + g + 8;
#pragma unroll
            for (int nt = 0; nt < 8; ++nt)
#pragma unroll
                for (int jj = 0; jj < 2; ++jj) {
                    const int col = j0 + nt * 8 + 2 * t4 + jj;
                    if (col > r0r) sc[nt][jj] = -1e30f;
                    if (col > r1r) sc[nt][2 + jj] = -1e30f;
                }
        }

        // partial max over S0
        float mx0 = -1e30f, mx1 = -1e30f;
#pragma unroll
        for (int nt = 0; nt < 8; ++nt) {
            mx0 = fmaxf(mx0, fmaxf(sc[nt][0], sc[nt][1]));
            mx1 = fmaxf(mx1, fmaxf(sc[nt][2], sc[nt][3]));
        }
        mx0 = fmaxf(mx0, __shfl_xor_sync(0xffffffffu, mx0, 1));
        mx0 = fmaxf(mx0, __shfl_xor_sync(0xffffffffu, mx0, 2));
        mx1 = fmaxf(mx1, __shfl_xor_sync(0xffffffffu, mx1, 1));
        mx1 = fmaxf(mx1, __shfl_xor_sync(0xffffffffu, mx1, 2));
        float mn0 = fmaxf(m0, mx0), mn1 = fmaxf(m1, mx1);

        // P0 packed now (frees sc for S1)
        uint32_t ap0[4][4];
#pragma unroll
        for (int s = 0; s < 4; ++s) {
            ap0[s][0] = ex2pack(sc[2 * s][0] - mn0, sc[2 * s][1] - mn0);
            ap0[s][1] = ex2pack(sc[2 * s][2] - mn1, sc[2 * s][3] - mn1);
            ap0[s][2] = ex2pack(sc[2 * s + 1][0] - mn0, sc[2 * s + 1][1] - mn0);
            ap0[s][3] = ex2pack(sc[2 * s + 1][2] - mn1, sc[2 * s + 1][3] - mn1);
        }

        // ================= S1 = Q K1^T (optional) =================
        if (do1) {
            const int j01 = j0 + 64;
#pragma unroll
            for (int nt = 0; nt < 8; ++nt)
#pragma unroll
                for (int q = 0; q < 4; ++q) sc[nt][q] = 0.f;
#pragma unroll
            for (int s = 0; s < 4; ++s) {
                const uint32_t xs = (uint32_t)s << 5;
                uint32_t bg[4][4];
#pragma unroll
                for (int np = 0; np < 4; ++np) LDM4(bg[np], (kb1 + paK[np]) ^ xs);
#pragma unroll
                for (int nt = 0; nt < 8; ++nt)
                    MMAH(sc[nt], qf[s], bg[nt >> 1][(nt & 1) * 2],
                         bg[nt >> 1][(nt & 1) * 2 + 1]);
            }
            if (j01 + 63 > rbase) {
                const int r0r = rbase + g, r1r = rbase + g + 8;
#pragma unroll
                for (int nt = 0; nt < 8; ++nt)
#pragma unroll
                    for (int jj = 0; jj < 2; ++jj) {
                        const int col = j01 + nt * 8 + 2 * t4 + jj;
                        if (col > r0r) sc[nt][jj] = -1e30f;
                        if (col > r1r) sc[nt][2 + jj] = -1e30f;
                    }
            }

            float nx0 = -1e30f, nx1 = -1e30f;
#pragma unroll
            for (int nt = 0; nt < 8; ++nt) {
                nx0 = fmaxf(nx0, fmaxf(sc[nt][0], sc[nt][1]));
                nx1 = fmaxf(nx1, fmaxf(sc[nt][2], sc[nt][3]));
            }
            nx0 = fmaxf(nx0, __shfl_xor_sync(0xffffffffu, nx0, 1));
            nx0 = fmaxf(nx0, __shfl_xor_sync(0xffffffffu, nx0, 2));
            nx1 = fmaxf(nx1, __shfl_xor_sync(0xffffffffu, nx1, 1));
            nx1 = fmaxf(nx1, __shfl_xor_sync(0xffffffffu, nx1, 2));

            const float f0 = fmaxf(mn0, nx0), f1 = fmaxf(mn1, nx1);
            // correct P0 into the final max domain
            const uint32_t d0 = packh(exp2f(mn0 - f0), exp2f(mn0 - f0));
            const uint32_t d1 = packh(exp2f(mn1 - f1), exp2f(mn1 - f1));
#pragma unroll
            for (int s = 0; s < 4; ++s) {
                ap0[s][0] = hmul2u(ap0[s][0], d0);
                ap0[s][1] = hmul2u(ap0[s][1], d1);
                ap0[s][2] = hmul2u(ap0[s][2], d0);
                ap0[s][3] = hmul2u(ap0[s][3], d1);
            }
            mn0 = f0; mn1 = f1;
        }

        // ================= single rescale per 128 cols =================
        const float a0 = exp2f(m0 - mn0), a1 = exp2f(m1 - mn1);
        m0 = mn0; m1 = mn1;
#pragma unroll
        for (int nt = 0; nt < 8; ++nt) {
            o[nt][0] *= a0; o[nt][1] *= a0;
            o[nt][2] *= a1; o[nt][3] *= a1;
        }
        ol[0] *= a0; ol[1] *= a0; ol[2] *= a1; ol[3] *= a1;

        // ================= PV for block 0 =================
#pragma unroll
        for (int s = 0; s < 4; ++s) {
            MMAH(ol, ap0[s], HONES, HONES);
            const uint32_t ro = (uint32_t)s * 2048;
            uint32_t bg[4][4];
#pragma unroll
            for (int np = 0; np < 4; ++np) LDM4T(bg[np], kb0 + paVt[np] + ro);
#pragma unroll
            for (int nt = 0; nt < 8; ++nt)
                MMAH(o[nt], ap0[s], bg[nt >> 1][(nt & 1) * 2],
                     bg[nt >> 1][(nt & 1) * 2 + 1]);
        }

        // ================= PV for block 1 (P1 built on the fly) =========
        if (do1) {
#pragma unroll
            for (int s = 0; s < 4; ++s) {
                uint32_t ap[4];
                ap[0] = ex2pack(sc[2 * s][0] - mn0, sc[2 * s][1] - mn0);
                ap[1] = ex2pack(sc[2 * s][2] - mn1, sc[2 * s][3] - mn1);
                ap[2] = ex2pack(sc[2 * s + 1][0] - mn0, sc[2 * s + 1][1] - mn0);
                ap[3] = ex2pack(sc[2 * s + 1][2] - mn1, sc[2 * s + 1][3] - mn1);

                MMAH(ol, ap, HONES, HONES);
                const uint32_t ro = (uint32_t)s * 2048;
                uint32_t bg[4][4];
#pragma unroll
                for (int np = 0; np < 4; ++np) LDM4T(bg[np], kb1 + paVt[np] + ro);
#pragma unroll
                for (int nt = 0; nt < 8; ++nt)
                    MMAH(o[nt], ap, bg[nt >> 1][(nt & 1) * 2],
                         bg[nt >> 1][(nt & 1) * 2 + 1]);
            }
        }
    }

    // ---- epilogue: normalize, write AO fp16 ----
    const float inv0 = 1.f / ol[0], inv1 = 1.f / ol[2];
    const size_t r0o = (base + rbase + g) * EMB + ch;
    const size_t r1o = (base + rbase + g + 8) * EMB + ch;
#pragma unroll
    for (int nt = 0; nt < 8; ++nt) {
        const int cc = nt * 8 + 2 * t4;
        *(uint32_t*)(g_ao + r0o + cc) = packh(o[nt][0] * inv0, o[nt][1] * inv0);
        *(uint32_t*)(g_ao + r1o + cc) = packh(o[nt][2] * inv1, o[nt][3] * inv1);
    }
}

// ---------------------------------------------------------------------------
extern "C" void kernel_launch(void* const* d_in, const int* in_sizes, int n_in,
                              void* d_out, int out_size)
{
    (void)in_sizes; (void)n_in; (void)out_size;
    const float* x  = (const float*)d_in[0];
    const float* Wk = (const float*)d_in[1];
    const float* bk = (const float*)d_in[2];
    const float* Wq = (const float*)d_in[3];
    const float* bq = (const float*)d_in[4];
    const float* Wv = (const float*)d_in[5];
    const float* bv = (const float*)d_in[6];
    const float* Wo = (const float*)d_in[7];
    const float* bo = (const float*)d_in[8];

    cudaFuncSetAttribute(flash_h_kernel,
                         cudaFuncAttributeMaxDynamicSharedMemorySize, FLASH_SMEM);
    cudaFuncSetAttribute(gemm_qkv_kernel,
                         cudaFuncAttributeMaxDynamicSharedMemorySize, GEMM_SMEM);
    cudaFuncSetAttribute(gemm_out_kernel,
                         cudaFuncAttributeMaxDynamicSharedMemorySize, GEMM_SMEM);

    conv_x_kernel<<<2048, 256>>>(x);
    conv_wt_kernel<<<dim3(32, 32, 4), 256>>>(Wq, Wk, Wv, Wo);
    gemm_qkv_kernel<<<dim3(8, 64, 3), 256, GEMM_SMEM>>>(bq, bk, bv);
    flash_h_kernel<<<dim3(16, 32), 256, FLASH_SMEM>>>();
    gemm_out_kernel<<<dim3(8, 64), 256, GEMM_SMEM>>>(bo, (float*)d_out);
}

// round 14
// speedup vs baseline: 1.0817x; 1.0817x over previous
#include <cuda_runtime.h>
#include <cuda_fp16.h>
#include <cstdint>

#define EMB   1024
#define CTXT  2048
#define MROWS 4096   // BATCH * CTXT

// ---------------------------------------------------------------------------
// Device scratch (allocation-free rule)
// ---------------------------------------------------------------------------
__device__ __half g_xh[MROWS * EMB];         // x, fp16
__device__ __half g_wt[4][EMB * EMB];        // W^T [n][k] fp16 (q,k,v,o)
__device__ __half g_Qh[MROWS * EMB];         // (xWq+bq) * log2e/32, fp16
__device__ __half g_Kh[MROWS * EMB];         // fp16
__device__ __half g_Vh[MROWS * EMB];         // fp16 (row-major)
__device__ __half g_ao[MROWS * EMB];         // attention out fp16

// ---------------------------------------------------------------------------
__device__ __forceinline__ uint32_t smem_u32(const void* p) {
    uint32_t a;
    asm("{ .reg .u64 t; cvta.to.shared.u64 t, %1; cvt.u32.u64 %0, t; }"
        : "=r"(a) : "l"(p));
    return a;
}
__device__ __forceinline__ void cpa16(uint32_t s, const void* g) {
    asm volatile("cp.async.cg.shared.global [%0], [%1], 16;" :: "r"(s), "l"(g));
}
__device__ __forceinline__ uint32_t packh(float x, float y) {
    __half2 h = __floats2half2_rn(x, y);
    return *(uint32_t*)&h;
}
// pack two fp32 (<=0) and take 2^x in fp16x2
__device__ __forceinline__ uint32_t ex2pack(float x, float y) {
    uint32_t d = packh(x, y), r;
    asm("ex2.approx.f16x2 %0, %1;" : "=r"(r) : "r"(d));
    return r;
}
__device__ __forceinline__ uint32_t hmul2u(uint32_t a, uint32_t b) {
    uint32_t r;
    asm("mul.f16x2 %0, %1, %2;" : "=r"(r) : "r"(a), "r"(b));
    return r;
}

#define LDM4(r, a)                                                            \
    asm volatile("ldmatrix.sync.aligned.m8n8.x4.shared.b16 {%0,%1,%2,%3}, [%4];" \
        : "=r"((r)[0]), "=r"((r)[1]), "=r"((r)[2]), "=r"((r)[3]) : "r"(a))

#define LDM4T(r, a)                                                           \
    asm volatile("ldmatrix.sync.aligned.m8n8.x4.trans.shared.b16 {%0,%1,%2,%3}, [%4];" \
        : "=r"((r)[0]), "=r"((r)[1]), "=r"((r)[2]), "=r"((r)[3]) : "r"(a))

#define MMAH(c, a, b0, b1)                                                    \
    asm volatile("mma.sync.aligned.m16n8k16.row.col.f32.f16.f16.f32 "         \
        "{%0,%1,%2,%3}, {%4,%5,%6,%7}, {%8,%9}, {%0,%1,%2,%3};"               \
        : "+f"((c)[0]), "+f"((c)[1]), "+f"((c)[2]), "+f"((c)[3])              \
        : "r"((a)[0]), "r"((a)[1]), "r"((a)[2]), "r"((a)[3]), "r"(b0), "r"(b1))

// ---------------------------------------------------------------------------
// Merged prep kernel: z<4 -> transpose+convert W slice z; z>=4 -> convert x.
// Grid: dim3(32, 32, 6), 256 threads.
// ---------------------------------------------------------------------------
__global__ __launch_bounds__(256) void prep_kernel(
    const float* __restrict__ x,
    const float* __restrict__ Wq, const float* __restrict__ Wk,
    const float* __restrict__ Wv, const float* __restrict__ Wo)
{
    const int z = blockIdx.z;
    if (z >= 4) {
        // conv_x: flat block 0..2047, 8 floats per thread
        const int blk = (z - 4) * 1024 + blockIdx.y * 32 + blockIdx.x;
        size_t i = ((size_t)blk * 256 + threadIdx.x) * 8;
        float4 v0 = *(const float4*)(x + i);
        float4 v1 = *(const float4*)(x + i + 4);
        uint32_t h[4];
        h[0] = packh(v0.x, v0.y); h[1] = packh(v0.z, v0.w);
        h[2] = packh(v1.x, v1.y); h[3] = packh(v1.z, v1.w);
        *(uint4*)(g_xh + i) = *(uint4*)h;
        return;
    }
    __shared__ float ts[32][33];
    const float* W = (z == 0) ? Wq : (z == 1) ? Wk : (z == 2) ? Wv : Wo;
    const int row0 = blockIdx.y << 5;   // k
    const int col0 = blockIdx.x << 5;   // n
    const int c = threadIdx.x & 31, r8 = threadIdx.x >> 5;
#pragma unroll
    for (int it = 0; it < 4; ++it) {
        int r = it * 8 + r8;
        ts[r][c] = W[(size_t)(row0 + r) * EMB + col0 + c];
    }
    __syncthreads();
#pragma unroll
    for (int it = 0; it < 4; ++it) {
        int r = it * 8 + r8;
        g_wt[z][(size_t)(col0 + r) * EMB + row0 + c] = __float2half(ts[c][r]);
    }
}

// ---------------------------------------------------------------------------
// FP16 GEMM: C[128,128] tile, K=1024. 8 warps (4M x 2N), warp tile 32x64.
// BK=64 halves (128B rows), 3-stage cp.async, single sync per chunk.
// ---------------------------------------------------------------------------
#define GSTAGE 32768                 // A 16KB + B 16KB
#define GEMM_SMEM (1024 + 3 * GSTAGE)

__device__ void h_gemm_body(const __half* __restrict__ A,
                            const __half* __restrict__ B,
                            const float* __restrict__ bias,
                            float* __restrict__ Cf,      // fp32 out
                            __half* __restrict__ Ch,     // fp16 out
                            float scale,
                            int row0, int col0)
{
    extern __shared__ char smraw[];
    const uint32_t sb = (smem_u32(smraw) + 1023u) & ~1023u;

    const int tid  = threadIdx.x;
    const int lane = tid & 31;
    const int wid  = tid >> 5;
    const int g    = lane >> 2;
    const int t4   = lane & 3;
    const int wm   = wid & 3;
    const int wn   = wid >> 2;

    float acc[2][8][4];
#pragma unroll
    for (int i = 0; i < 2; ++i)
#pragma unroll
        for (int j = 0; j < 8; ++j)
#pragma unroll
            for (int q = 0; q < 4; ++q) acc[i][j][q] = 0.f;

    uint32_t paA[2], paB[4];
    {
        const int rrA = (lane & 7) + ((lane >> 3) & 1) * 8;
        const int cpA = (lane >> 4) & 1;
#pragma unroll
        for (int ma = 0; ma < 2; ++ma) {
            int r = wm * 32 + ma * 16 + rrA;
            paA[ma] = r * 128 + ((cpA ^ (r & 1)) << 4) + (((r >> 1) & 3) << 5);
        }
        const int rrB = (lane & 7) + ((lane >> 4) & 1) * 8;
        const int cpB = (lane >> 3) & 1;
#pragma unroll
        for (int np = 0; np < 4; ++np) {
            int n = wn * 64 + np * 16 + rrB;
            paB[np] = 16384 + n * 128 + ((cpB ^ (n & 1)) << 4) + (((n >> 1) & 3) << 5);
        }
    }

    auto issue = [&](int kc, int st) {
        const uint32_t sbase = sb + st * GSTAGE;
#pragma unroll
        for (int it = 0; it < 8; ++it) {
            const int id = it * 256 + tid;
            const int mat = id >> 10;
            const int idx = id & 1023;
            const int r = idx >> 3, c = idx & 7;
            const __half* src = (mat ? B + (size_t)(col0 + r) * EMB
                                     : A + (size_t)(row0 + r) * EMB) + kc + c * 8;
            cpa16(sbase + mat * 16384 + r * 128 + ((c ^ (r & 7)) << 4), src);
        }
        asm volatile("cp.async.commit_group;");
    };

    issue(0, 0);
    issue(64, 1);

    for (int c = 0; c < EMB / 64; ++c) {
        if (c + 1 < EMB / 64) {
            asm volatile("cp.async.wait_group 1;");
        } else {
            asm volatile("cp.async.wait_group 0;");
        }
        __syncthreads();
        if (c + 2 < EMB / 64) issue((c + 2) * 64, (c + 2) % 3);

        const uint32_t stb = sb + (c % 3) * GSTAGE;
#pragma unroll
        for (int s = 0; s < 4; ++s) {
            const uint32_t xs = (uint32_t)s << 5;
            uint32_t a[2][4], bg[4][4];
            LDM4(a[0], (stb + paA[0]) ^ xs);
            LDM4(a[1], (stb + paA[1]) ^ xs);
#pragma unroll
            for (int np = 0; np < 4; ++np) LDM4(bg[np], (stb + paB[np]) ^ xs);
#pragma unroll
            for (int nt = 0; nt < 8; ++nt) {
                const uint32_t b0 = bg[nt >> 1][(nt & 1) * 2];
                const uint32_t b1 = bg[nt >> 1][(nt & 1) * 2 + 1];
                MMAH(acc[0][nt], a[0], b0, b1);
                MMAH(acc[1][nt], a[1], b0, b1);
            }
        }
    }

#pragma unroll
    for (int nt = 0; nt < 8; ++nt) {
        const int n = col0 + wn * 64 + nt * 8 + t4 * 2;
        const float bz0 = bias[n], bz1 = bias[n + 1];
#pragma unroll
        for (int ma = 0; ma < 2; ++ma) {
            const int mr = row0 + wm * 32 + ma * 16 + g;
            float p0 = acc[ma][nt][0] + bz0, p1 = acc[ma][nt][1] + bz1;
            float p2 = acc[ma][nt][2] + bz0, p3 = acc[ma][nt][3] + bz1;
            if (Ch) {
                *(uint32_t*)(Ch + (size_t)mr * EMB + n) = packh(p0 * scale, p1 * scale);
                *(uint32_t*)(Ch + (size_t)(mr + 8) * EMB + n) = packh(p2 * scale, p3 * scale);
            } else {
                *(float2*)(Cf + (size_t)mr * EMB + n) = float2{p0, p1};
                *(float2*)(Cf + (size_t)(mr + 8) * EMB + n) = float2{p2, p3};
            }
        }
    }
}

__global__ __launch_bounds__(256) void gemm_qkv_kernel(
    const float* __restrict__ bq, const float* __restrict__ bk,
    const float* __restrict__ bv)
{
    const int z = blockIdx.z;
    const int r0 = blockIdx.y << 7, c0 = blockIdx.x << 7;
    if (z == 0)   // fold 1/sqrt(1024) * log2(e) into Q
        h_gemm_body(g_xh, g_wt[0], bq, nullptr, g_Qh, 0.0450842190f, r0, c0);
    else if (z == 1)
        h_gemm_body(g_xh, g_wt[1], bk, nullptr, g_Kh, 1.0f, r0, c0);
    else
        h_gemm_body(g_xh, g_wt[2], bv, nullptr, g_Vh, 1.0f, r0, c0);
}

__global__ __launch_bounds__(256) void gemm_out_kernel(
    const float* __restrict__ bo, float* __restrict__ out)
{
    h_gemm_body(g_ao, g_wt[3], bo, out, nullptr, 1.0f,
                blockIdx.y << 7, blockIdx.x << 7);
}

// ---------------------------------------------------------------------------
// FP16 flash attention, log2-domain softmax, fp16x2 ex2, ones-MMA row sums.
// BM=128 (8 warps x m16), fused BN=128 softmax (one rescale per 2 j-blocks).
// Grid: (T/128, B*H). smem: Q 16KB + 4 KV stages (K+V) 16KB each.
// ---------------------------------------------------------------------------
#define FSTG0 16384
#define FSTGSZ 16384
#define FLASH_SMEM (1024 + FSTG0 + 4 * FSTGSZ)   // 83 KB -> 2 CTAs/SM
#define HONES 0x3C003C00u   // half2(1.0, 1.0)

__global__ __launch_bounds__(256, 2) void flash_h_kernel()
{
    extern __shared__ char fsmraw[];
    const uint32_t sb = (smem_u32(fsmraw) + 1023u) & ~1023u;

    const int tid = threadIdx.x;
    const int lane = tid & 31, wid = tid >> 5;
    const int g = lane >> 2, t4 = lane & 3;
    const int bh = blockIdx.y, b = bh >> 4;
    const int qb = (int)(gridDim.x - 1 - blockIdx.x);   // longest first
    const int q0 = qb << 7;
    const size_t base = (size_t)b * CTXT;
    const int ch = (bh & 15) << 6;
    const int rbase = q0 + wid * 16;

    uint32_t paQ, paK[4], paVt[4];
    {
        const int rrA = (lane & 7) + ((lane >> 3) & 1) * 8;
        const int cpA = (lane >> 4) & 1;
        const int r = wid * 16 + rrA;
        paQ = r * 128 + ((cpA ^ (r & 1)) << 4) + (((r >> 1) & 3) << 5);

        const int rrB = (lane & 7) + ((lane >> 4) & 1) * 8;
        const int cpB = (lane >> 3) & 1;
#pragma unroll
        for (int np = 0; np < 4; ++np) {
            int n = np * 16 + rrB;
            paK[np] = n * 128 + ((cpB ^ (n & 1)) << 4) + (((n >> 1) & 3) << 5);
        }
        const int rrV = (lane & 7) + ((lane >> 3) & 1) * 8;   // j within 16
        const int cpV = (lane >> 4) & 1;                      // d chunk within 16
#pragma unroll
        for (int np = 0; np < 4; ++np) {
            int c = 2 * np + cpV;
            paVt[np] = 8192 + rrV * 128 + ((c ^ (rrV & 7)) << 4);
        }
    }

    // Q tile (group 0)
    for (int i = tid; i < 1024; i += 256) {
        const int r = i >> 3, c = i & 7;
        cpa16(sb + r * 128 + ((c ^ (r & 7)) << 4),
              g_Qh + (base + q0 + r) * EMB + ch + c * 8);
    }
    asm volatile("cp.async.commit_group;");

    auto issue_kv = [&](int j0, int st) {
        const uint32_t kb = sb + FSTG0 + st * FSTGSZ;
        for (int i = tid; i < 512; i += 256) {
            const int r = i >> 3, c = i & 7;
            const uint32_t so = r * 128 + ((c ^ (r & 7)) << 4);
            cpa16(kb + so, g_Kh + (base + j0 + r) * EMB + ch + c * 8);
            cpa16(kb + 8192 + so, g_Vh + (base + j0 + r) * EMB + ch + c * 8);
        }
        asm volatile("cp.async.commit_group;");
    };

    const int nblocks = qb * 2 + 2;   // always even
    issue_kv(0, 0);
    issue_kv(64, 1);

    uint32_t qf[4][4];                 // Q fragments, loaded once
    float o[8][4];
    float ol[4] = {0.f, 0.f, 0.f, 0.f};
#pragma unroll
    for (int nt = 0; nt < 8; ++nt)
#pragma unroll
        for (int q = 0; q < 4; ++q) o[nt][q] = 0.f;
    float m0 = -1e30f, m1 = -1e30f;

    for (int jb = 0; jb < nblocks; jb += 2) {
        asm volatile("cp.async.wait_group 0;");
        __syncthreads();
        if (jb == 0) {
#pragma unroll
            for (int s = 0; s < 4; ++s) LDM4(qf[s], (sb + paQ) ^ ((uint32_t)s << 5));
        }
        // prefetch next pair into stages consumed LAST pair (sync above protects)
        if (jb + 2 < nblocks) issue_kv((jb + 2) << 6, (jb + 2) & 3);
        if (jb + 3 < nblocks) issue_kv((jb + 3) << 6, (jb + 3) & 3);

        const int j0 = jb << 6;
        if (j0 > rbase + 15) continue;        // pair fully masked for this warp
        const bool do1 = (j0 + 64) <= rbase + 15;
        const uint32_t kb0 = sb + FSTG0 + (jb & 3) * FSTGSZ;
        const uint32_t kb1 = sb + FSTG0 + ((jb + 1) & 3) * FSTGSZ;

        float sc[8][4];

        // ================= S0 = Q K0^T =================
#pragma unroll
        for (int nt = 0; nt < 8; ++nt)
#pragma unroll
            for (int q = 0; q < 4; ++q) sc[nt][q] = 0.f;
#pragma unroll
        for (int s = 0; s < 4; ++s) {
            const uint32_t xs = (uint32_t)s << 5;
            uint32_t bg[4][4];
#pragma unroll
            for (int np = 0; np < 4; ++np) LDM4(bg[np], (kb0 + paK[np]) ^ xs);
#pragma unroll
            for (int nt = 0; nt < 8; ++nt)
                MMAH(sc[nt], qf[s], bg[nt >> 1][(nt & 1) * 2],
                     bg[nt >> 1][(nt & 1) * 2 + 1]);
        }
        if (j0 + 63 > rbase) {
            const int r0r = rbase + g, r1r = rbase + g + 8;
#pragma unroll
            for (int nt = 0; nt < 8; ++nt)
#pragma unroll
                for (int jj = 0; jj < 2; ++jj) {
                    const int col = j0 + nt * 8 + 2 * t4 + jj;
                    if (col > r0r) sc[nt][jj] = -1e30f;
                    if (col > r1r) sc[nt][2 + jj] = -1e30f;
                }
        }

        // partial max over S0
        float mx0 = -1e30f, mx1 = -1e30f;
#pragma unroll
        for (int nt = 0; nt < 8; ++nt) {
            mx0 = fmaxf(mx0, fmaxf(sc[nt][0], sc[nt][1]));
            mx1 = fmaxf(mx1, fmaxf(sc[nt][2], sc[nt][3]));
        }
        mx0 = fmaxf(mx0, __shfl_xor_sync(0xffffffffu, mx0, 1));
        mx0 = fmaxf(mx0, __shfl_xor_sync(0xffffffffu, mx0, 2));
        mx1 = fmaxf(mx1, __shfl_xor_sync(0xffffffffu, mx1, 1));
        mx1 = fmaxf(mx1, __shfl_xor_sync(0xffffffffu, mx1, 2));
        float mn0 = fmaxf(m0, mx0), mn1 = fmaxf(m1, mx1);

        // P0 packed now (frees sc for S1)
        uint32_t ap0[4][4];
#pragma unroll
        for (int s = 0; s < 4; ++s) {
            ap0[s][0] = ex2pack(sc[2 * s][0] - mn0, sc[2 * s][1] - mn0);
            ap0[s][1] = ex2pack(sc[2 * s][2] - mn1, sc[2 * s][3] - mn1);
            ap0[s][2] = ex2pack(sc[2 * s + 1][0] - mn0, sc[2 * s + 1][1] - mn0);
            ap0[s][3] = ex2pack(sc[2 * s + 1][2] - mn1, sc[2 * s + 1][3] - mn1);
        }

        // ================= S1 = Q K1^T (optional) =================
        if (do1) {
            const int j01 = j0 + 64;
#pragma unroll
            for (int nt = 0; nt < 8; ++nt)
#pragma unroll
                for (int q = 0; q < 4; ++q) sc[nt][q] = 0.f;
#pragma unroll
            for (int s = 0; s < 4; ++s) {
                const uint32_t xs = (uint32_t)s << 5;
                uint32_t bg[4][4];
#pragma unroll
                for (int np = 0; np < 4; ++np) LDM4(bg[np], (kb1 + paK[np]) ^ xs);
#pragma unroll
                for (int nt = 0; nt < 8; ++nt)
                    MMAH(sc[nt], qf[s], bg[nt >> 1][(nt & 1) * 2],
                         bg[nt >> 1][(nt & 1) * 2 + 1]);
            }
            if (j01 + 63 > rbase) {
                const int r0r = rbase + g, r1r = rbase + g + 8;
#pragma unroll
                for (int nt = 0; nt < 8; ++nt)
#pragma unroll
                    for (int jj = 0; jj < 2; ++jj) {
                        const int col = j01 + nt * 8 + 2 * t4 + jj;
                        if (col > r0r) sc[nt][jj] = -1e30f;
                        if (col > r1r) sc[nt][2 + jj] = -1e30f;
                    }
            }

            float nx0 = -1e30f, nx1 = -1e30f;
#pragma unroll
            for (int nt = 0; nt < 8; ++nt) {
                nx0 = fmaxf(nx0, fmaxf(sc[nt][0], sc[nt][1]));
                nx1 = fmaxf(nx1, fmaxf(sc[nt][2], sc[nt][3]));
            }
            nx0 = fmaxf(nx0, __shfl_xor_sync(0xffffffffu, nx0, 1));
            nx0 = fmaxf(nx0, __shfl_xor_sync(0xffffffffu, nx0, 2));
            nx1 = fmaxf(nx1, __shfl_xor_sync(0xffffffffu, nx1, 1));
            nx1 = fmaxf(nx1, __shfl_xor_sync(0xffffffffu, nx1, 2));

            const float f0 = fmaxf(mn0, nx0), f1 = fmaxf(mn1, nx1);
            // correct P0 into the final max domain
            const uint32_t d0 = packh(exp2f(mn0 - f0), exp2f(mn0 - f0));
            const uint32_t d1 = packh(exp2f(mn1 - f1), exp2f(mn1 - f1));
#pragma unroll
            for (int s = 0; s < 4; ++s) {
                ap0[s][0] = hmul2u(ap0[s][0], d0);
                ap0[s][1] = hmul2u(ap0[s][1], d1);
                ap0[s][2] = hmul2u(ap0[s][2], d0);
                ap0[s][3] = hmul2u(ap0[s][3], d1);
            }
            mn0 = f0; mn1 = f1;
        }

        // ================= single rescale per 128 cols =================
        const float a0 = exp2f(m0 - mn0), a1 = exp2f(m1 - mn1);
        m0 = mn0; m1 = mn1;
#pragma unroll
        for (int nt = 0; nt < 8; ++nt) {
            o[nt][0] *= a0; o[nt][1] *= a0;
            o[nt][2] *= a1; o[nt][3] *= a1;
        }
        ol[0] *= a0; ol[1] *= a0; ol[2] *= a1; ol[3] *= a1;

        // ================= PV for block 0 =================
#pragma unroll
        for (int s = 0; s < 4; ++s) {
            MMAH(ol, ap0[s], HONES, HONES);
            const uint32_t ro = (uint32_t)s * 2048;
            uint32_t bg[4][4];
#pragma unroll
            for (int np = 0; np < 4; ++np) LDM4T(bg[np], kb0 + paVt[np] + ro);
#pragma unroll
            for (int nt = 0; nt < 8; ++nt)
                MMAH(o[nt], ap0[s], bg[nt >> 1][(nt & 1) * 2],
                     bg[nt >> 1][(nt & 1) * 2 + 1]);
        }

        // ================= PV for block 1 (P1 built on the fly) =========
        if (do1) {
#pragma unroll
            for (int s = 0; s < 4; ++s) {
                uint32_t ap[4];
                ap[0] = ex2pack(sc[2 * s][0] - mn0, sc[2 * s][1] - mn0);
                ap[1] = ex2pack(sc[2 * s][2] - mn1, sc[2 * s][3] - mn1);
                ap[2] = ex2pack(sc[2 * s + 1][0] - mn0, sc[2 * s + 1][1] - mn0);
                ap[3] = ex2pack(sc[2 * s + 1][2] - mn1, sc[2 * s + 1][3] - mn1);

                MMAH(ol, ap, HONES, HONES);
                const uint32_t ro = (uint32_t)s * 2048;
                uint32_t bg[4][4];
#pragma unroll
                for (int np = 0; np < 4; ++np) LDM4T(bg[np], kb1 + paVt[np] + ro);
#pragma unroll
                for (int nt = 0; nt < 8; ++nt)
                    MMAH(o[nt], ap, bg[nt >> 1][(nt & 1) * 2],
                         bg[nt >> 1][(nt & 1) * 2 + 1]);
            }
        }
    }

    // ---- epilogue: normalize, write AO fp16 ----
    const float inv0 = 1.f / ol[0], inv1 = 1.f / ol[2];
    const size_t r0o = (base + rbase + g) * EMB + ch;
    const size_t r1o = (base + rbase + g + 8) * EMB + ch;
#pragma unroll
    for (int nt = 0; nt < 8; ++nt) {
        const int cc = nt * 8 + 2 * t4;
        *(uint32_t*)(g_ao + r0o + cc) = packh(o[nt][0] * inv0, o[nt][1] * inv0);
        *(uint32_t*)(g_ao + r1o + cc) = packh(o[nt][2] * inv1, o[nt][3] * inv1);
    }
}

// ---------------------------------------------------------------------------
extern "C" void kernel_launch(void* const* d_in, const int* in_sizes, int n_in,
                              void* d_out, int out_size)
{
    (void)in_sizes; (void)n_in; (void)out_size;
    const float* x  = (const float*)d_in[0];
    const float* Wk = (const float*)d_in[1];
    const float* bk = (const float*)d_in[2];
    const float* Wq = (const float*)d_in[3];
    const float* bq = (const float*)d_in[4];
    const float* Wv = (const float*)d_in[5];
    const float* bv = (const float*)d_in[6];
    const float* Wo = (const float*)d_in[7];
    const float* bo = (const float*)d_in[8];

    cudaFuncSetAttribute(flash_h_kernel,
                         cudaFuncAttributeMaxDynamicSharedMemorySize, FLASH_SMEM);
    cudaFuncSetAttribute(gemm_qkv_kernel,
                         cudaFuncAttributeMaxDynamicSharedMemorySize, GEMM_SMEM);
    cudaFuncSetAttribute(gemm_out_kernel,
                         cudaFuncAttributeMaxDynamicSharedMemorySize, GEMM_SMEM);

    prep_kernel<<<dim3(32, 32, 6), 256>>>(x, Wq, Wk, Wv, Wo);
    gemm_qkv_kernel<<<dim3(8, 32, 3), 256, GEMM_SMEM>>>(bq, bk, bv);
    flash_h_kernel<<<dim3(16, 32), 256, FLASH_SMEM>>>();
    gemm_out_kernel<<<dim3(8, 32), 256, GEMM_SMEM>>>(bo, (float*)d_out);
}